// round 1
// baseline (speedup 1.0000x reference)
#include <cuda_runtime.h>
#include <cstdint>

#define NUM_EDGE  14
#define NUM_NODES 10000
#define BATCH     8192
#define EDGE_IN   1536
#define HET_IN    1792
#define DOUT      128

// Scratch for the intermediate aggregation, already laid out as
// agg[b][e*128 + k]  (i.e. the transpose/reshape in the reference).
__device__ float g_agg[(size_t)BATCH * HET_IN];

// Round-to-nearest tf32 (keeps bits in a float slot). Using RN is load-bearing:
// letting the MMA truncate raw fp32 bits biases every product low by ~2^-10.
__device__ __forceinline__ float f2tf(float x) {
    uint32_t u;
    asm("cvt.rna.tf32.f32 %0, %1;" : "=r"(u) : "f"(x));
    return __uint_as_float(u);
}

__device__ __forceinline__ void mma_tf32(float* c, const uint32_t* a, const uint32_t* b) {
    asm volatile(
        "mma.sync.aligned.m16n8k8.row.col.f32.tf32.tf32.f32 "
        "{%0,%1,%2,%3}, {%4,%5,%6,%7}, {%8,%9}, {%0,%1,%2,%3};\n"
        : "+f"(c[0]), "+f"(c[1]), "+f"(c[2]), "+f"(c[3])
        : "r"(a[0]), "r"(a[1]), "r"(a[2]), "r"(a[3]),
          "r"(b[0]), "r"(b[1]));
}

// One kernel body for both GEMMs.
// EDGE=true : A = features[e] gathered by gid, W = W_edge[e], out = g_agg (col offset e*128)
// EDGE=false: A = g_agg, W = W_het, out = final output
template <bool EDGE>
__global__ void __launch_bounds__(256) hetagg_gemm(
    const float* __restrict__ Ain,
    const float* __restrict__ Wall,
    const float* __restrict__ ball,
    const int*   __restrict__ gid,
    float*       __restrict__ outFinal)
{
    constexpr int K   = EDGE ? EDGE_IN : HET_IN;
    constexpr int LDA = EDGE ? EDGE_IN : HET_IN;
    constexpr int KT  = K / 16;

    const int e = EDGE ? blockIdx.y : 0;
    const float* A    = EDGE ? (Ain + (size_t)e * NUM_NODES * EDGE_IN) : g_agg;
    const float* W    = EDGE ? (Wall + (size_t)e * EDGE_IN * DOUT)     : Wall;
    const float* bias = EDGE ? (ball + e * DOUT)                       : ball;
    float* outp       = EDGE ? g_agg : outFinal;
    const int outLd   = EDGE ? HET_IN : DOUT;
    const int colOff  = EDGE ? e * DOUT : 0;

    // Padded smem tiles: strides chosen so the mma fragment LDS pattern is
    // bank-conflict-free (A: 20*r+c covers all 32 banks; B: 136*k+n -> 8k+n).
    __shared__ float As[2][128][20];
    __shared__ float Bs[2][16][136];
    __shared__ int   rowIdx[128];

    const int tid  = threadIdx.x;
    const int lane = tid & 31;
    const int warp = tid >> 5;
    const int wm   = warp >> 2;   // 0..1  (64-row band)
    const int wn   = warp & 3;    // 0..3  (32-col band)
    const int m0   = blockIdx.x * 128;

    if (tid < 128) rowIdx[tid] = EDGE ? gid[m0 + tid] : (m0 + tid);
    __syncthreads();

    // Global->smem loader mapping (256 threads, 2 float4 each per operand)
    const int la_m = tid >> 1;
    const int la_k = (tid & 1) * 8;
    const float* aRow = A + (size_t)rowIdx[la_m] * LDA;
    const int lb_k = tid >> 4;
    const int lb_n = (tid & 15) * 8;
    const float* bRow = W + lb_k * DOUT + lb_n;

    float4 av0, av1, bv0, bv1;
    av0 = *(const float4*)(aRow + la_k);
    av1 = *(const float4*)(aRow + la_k + 4);
    bv0 = *(const float4*)(bRow);
    bv1 = *(const float4*)(bRow + 4);

    float acc[4][4][4];
    #pragma unroll
    for (int i = 0; i < 4; ++i)
        #pragma unroll
        for (int j = 0; j < 4; ++j)
            #pragma unroll
            for (int q = 0; q < 4; ++q) acc[i][j][q] = 0.f;

    int buf = 0;
    {
        float* ap = &As[0][la_m][la_k];
        ap[0] = f2tf(av0.x); ap[1] = f2tf(av0.y); ap[2] = f2tf(av0.z); ap[3] = f2tf(av0.w);
        ap[4] = f2tf(av1.x); ap[5] = f2tf(av1.y); ap[6] = f2tf(av1.z); ap[7] = f2tf(av1.w);
        float* bp = &Bs[0][lb_k][lb_n];
        bp[0] = f2tf(bv0.x); bp[1] = f2tf(bv0.y); bp[2] = f2tf(bv0.z); bp[3] = f2tf(bv0.w);
        bp[4] = f2tf(bv1.x); bp[5] = f2tf(bv1.y); bp[6] = f2tf(bv1.z); bp[7] = f2tf(bv1.w);
    }
    __syncthreads();

    for (int kt = 0; kt < KT; ++kt) {
        // Prefetch next K-tile from global into registers (overlaps compute)
        if (kt + 1 < KT) {
            const int k0 = (kt + 1) * 16;
            av0 = *(const float4*)(aRow + k0 + la_k);
            av1 = *(const float4*)(aRow + k0 + la_k + 4);
            bv0 = *(const float4*)(bRow + (size_t)k0 * DOUT);
            bv1 = *(const float4*)(bRow + (size_t)k0 * DOUT + 4);
        }

        // Compute on current buffer: 2 k8-steps, 4x4 m16n8 tiles per warp
        #pragma unroll
        for (int kk = 0; kk < 2; ++kk) {
            const int k8 = kk * 8;
            uint32_t af[4][4], bf[4][2];
            const int ar = lane >> 2;
            const int ac = k8 + (lane & 3);
            #pragma unroll
            for (int mt = 0; mt < 4; ++mt) {
                const int r = wm * 64 + mt * 16 + ar;
                af[mt][0] = __float_as_uint(As[buf][r][ac]);
                af[mt][1] = __float_as_uint(As[buf][r + 8][ac]);
                af[mt][2] = __float_as_uint(As[buf][r][ac + 4]);
                af[mt][3] = __float_as_uint(As[buf][r + 8][ac + 4]);
            }
            #pragma unroll
            for (int nt = 0; nt < 4; ++nt) {
                const int n = wn * 32 + nt * 8 + (lane >> 2);
                bf[nt][0] = __float_as_uint(Bs[buf][k8 + (lane & 3)][n]);
                bf[nt][1] = __float_as_uint(Bs[buf][k8 + (lane & 3) + 4][n]);
            }
            #pragma unroll
            for (int mt = 0; mt < 4; ++mt)
                #pragma unroll
                for (int nt = 0; nt < 4; ++nt)
                    mma_tf32(acc[mt][nt], af[mt], bf[nt]);
        }

        // Stage next tile into the other buffer
        if (kt + 1 < KT) {
            const int nb = buf ^ 1;
            float* ap = &As[nb][la_m][la_k];
            ap[0] = f2tf(av0.x); ap[1] = f2tf(av0.y); ap[2] = f2tf(av0.z); ap[3] = f2tf(av0.w);
            ap[4] = f2tf(av1.x); ap[5] = f2tf(av1.y); ap[6] = f2tf(av1.z); ap[7] = f2tf(av1.w);
            float* bp = &Bs[nb][lb_k][lb_n];
            bp[0] = f2tf(bv0.x); bp[1] = f2tf(bv0.y); bp[2] = f2tf(bv0.z); bp[3] = f2tf(bv0.w);
            bp[4] = f2tf(bv1.x); bp[5] = f2tf(bv1.y); bp[6] = f2tf(bv1.z); bp[7] = f2tf(bv1.w);
            __syncthreads();
            buf = nb;
        }
    }

    // Epilogue: bias + leaky_relu(0.01) + store (float2 pairs)
    #pragma unroll
    for (int mt = 0; mt < 4; ++mt) {
        const int row = m0 + wm * 64 + mt * 16 + (lane >> 2);
        #pragma unroll
        for (int nt = 0; nt < 4; ++nt) {
            const int col = wn * 32 + nt * 8 + (lane & 3) * 2;
            const float b0 = bias[col], b1 = bias[col + 1];
            float x0 = acc[mt][nt][0] + b0; x0 = x0 > 0.f ? x0 : 0.01f * x0;
            float x1 = acc[mt][nt][1] + b1; x1 = x1 > 0.f ? x1 : 0.01f * x1;
            float x2 = acc[mt][nt][2] + b0; x2 = x2 > 0.f ? x2 : 0.01f * x2;
            float x3 = acc[mt][nt][3] + b1; x3 = x3 > 0.f ? x3 : 0.01f * x3;
            *(float2*)&outp[(size_t)row * outLd + colOff + col]       = make_float2(x0, x1);
            *(float2*)&outp[(size_t)(row + 8) * outLd + colOff + col] = make_float2(x2, x3);
        }
    }
}

extern "C" void kernel_launch(void* const* d_in, const int* in_sizes, int n_in,
                              void* d_out, int out_size) {
    const float* features = (const float*)d_in[0];
    const float* W_edge   = (const float*)d_in[1];
    const float* b_edge   = (const float*)d_in[2];
    const float* W_het    = (const float*)d_in[3];
    const float* b_het    = (const float*)d_in[4];
    const int*   gid      = (const int*)d_in[5];
    float* out = (float*)d_out;

    dim3 g1(BATCH / 128, NUM_EDGE);
    hetagg_gemm<true><<<g1, 256>>>(features, W_edge, b_edge, gid, out);

    dim3 g2(BATCH / 128, 1);
    hetagg_gemm<false><<<g2, 256>>>(nullptr, W_het, b_het, nullptr, out);
}

// round 2
// speedup vs baseline: 1.1697x; 1.1697x over previous
#include <cuda_runtime.h>
#include <cstdint>

#define NUM_EDGE  14
#define NUM_NODES 10000
#define BATCH     8192
#define EDGE_IN   1536
#define HET_IN    1792
#define DOUT      128

// Intermediate aggregation, laid out as agg[b][e*128 + k].
__device__ float g_agg[(size_t)BATCH * HET_IN];

// RN tf32 conversion (load-bearing: raw-bit truncation biases products ~1e-3 low).
__device__ __forceinline__ uint32_t f2tf_u(float x) {
    uint32_t u;
    asm("cvt.rna.tf32.f32 %0, %1;" : "=r"(u) : "f"(x));
    return u;
}

__device__ __forceinline__ void cp16(uint32_t s, const void* g) {
    asm volatile("cp.async.cg.shared.global [%0], [%1], 16;\n" :: "r"(s), "l"(g));
}
__device__ __forceinline__ void cp_commit() { asm volatile("cp.async.commit_group;\n"); }
template <int N> __device__ __forceinline__ void cp_wait() {
    asm volatile("cp.async.wait_group %0;\n" :: "n"(N));
}

__device__ __forceinline__ void mma_tf32(float* c, const uint32_t* a, const uint32_t* b) {
    asm volatile(
        "mma.sync.aligned.m16n8k8.row.col.f32.tf32.tf32.f32 "
        "{%0,%1,%2,%3}, {%4,%5,%6,%7}, {%8,%9}, {%0,%1,%2,%3};\n"
        : "+f"(c[0]), "+f"(c[1]), "+f"(c[2]), "+f"(c[3])
        : "r"(a[0]), "r"(a[1]), "r"(a[2]), "r"(a[3]),
          "r"(b[0]), "r"(b[1]));
}

// EDGE=true : A = features[e] gathered by gid, W = W_edge[e], out -> g_agg col e*128. BM=128.
// EDGE=false: A = g_agg,                      W = W_het,      out -> final.        BM=64.
template <bool EDGE>
__global__ void __launch_bounds__(256, 2) hetagg_gemm(
    const float* __restrict__ Ain,
    const float* __restrict__ Wall,
    const float* __restrict__ ball,
    const int*   __restrict__ gid,
    float*       __restrict__ outFinal)
{
    constexpr int BM  = EDGE ? 128 : 64;
    constexpr int WMT = EDGE ? 4 : 2;          // m16 tiles per warp
    constexpr int K   = EDGE ? EDGE_IN : HET_IN;
    constexpr int LDA = EDGE ? EDGE_IN : HET_IN;
    constexpr int KT  = K / 16;
    constexpr int AST = 20;                    // A smem row stride (floats): conflict-free + 16B-aligned
    constexpr int BST = 136;                   // B smem row stride
    constexpr int A_STAGE = BM * AST;
    constexpr int B_STAGE = 16 * BST;
    constexpr int STAGES = 3;

    extern __shared__ float smem[];
    float* AsBase = smem;                                  // [STAGES][BM][AST]
    float* BsBase = smem + STAGES * A_STAGE;               // [STAGES][16][BST]
    int*   rowIdx = (int*)(smem + STAGES * (A_STAGE + B_STAGE));

    const int e = EDGE ? blockIdx.y : 0;
    const float* A    = EDGE ? (Ain + (size_t)e * NUM_NODES * EDGE_IN) : g_agg;
    const float* W    = EDGE ? (Wall + (size_t)e * EDGE_IN * DOUT)     : Wall;
    const float* bias = EDGE ? (ball + e * DOUT)                       : ball;
    float* outp       = EDGE ? g_agg : outFinal;
    const int outLd   = EDGE ? HET_IN : DOUT;
    const int colOff  = EDGE ? e * DOUT : 0;

    const int tid  = threadIdx.x;
    const int lane = tid & 31;
    const int warp = tid >> 5;
    const int wm   = warp >> 2;                // 0..1
    const int wn   = warp & 3;                 // 0..3
    const int m0   = blockIdx.x * BM;

    if (tid < BM) rowIdx[tid] = EDGE ? gid[m0 + tid] : (m0 + tid);
    __syncthreads();

    // cp.async loader mapping
    //   EDGE: A tile 128x16 -> thread t: row t>>1, cols (t&1)*8 .. +8  (two 16B chunks)
    //   HET : A tile  64x16 -> thread t: row t>>2, cols (t&3)*4 .. +4  (one 16B chunk)
    //   B tile 16x128        -> thread t: row t>>4, cols (t&15)*8 .. +8 (two 16B chunks)
    const int la_m = EDGE ? (tid >> 1) : (tid >> 2);
    const int la_c = EDGE ? ((tid & 1) * 8) : ((tid & 3) * 4);
    const float* aBase = A + (size_t)rowIdx[la_m] * LDA + la_c;
    const int lb_r = tid >> 4;
    const int lb_c = (tid & 15) * 8;
    const float* bBase = W + (size_t)lb_r * DOUT + lb_c;

    const uint32_t aSm = (uint32_t)__cvta_generic_to_shared(AsBase) + (la_m * AST + la_c) * 4;
    const uint32_t bSm = (uint32_t)__cvta_generic_to_shared(BsBase) + (lb_r * BST + lb_c) * 4;

    auto issue_stage = [&](int s, int kt) {
        const float* ag = aBase + kt * 16;
        cp16(aSm + s * (A_STAGE * 4), ag);
        if (EDGE) cp16(aSm + s * (A_STAGE * 4) + 16, ag + 4);
        const float* bg = bBase + (size_t)(kt * 16) * DOUT;
        cp16(bSm + s * (B_STAGE * 4), bg);
        cp16(bSm + s * (B_STAGE * 4) + 16, bg + 4);
    };

    float acc[WMT][4][4];
    #pragma unroll
    for (int i = 0; i < WMT; ++i)
        #pragma unroll
        for (int j = 0; j < 4; ++j)
            #pragma unroll
            for (int q = 0; q < 4; ++q) acc[i][j][q] = 0.f;

    // Prologue: stages 0 and 1 in flight
    issue_stage(0, 0); cp_commit();
    issue_stage(1, 1); cp_commit();

    const int ar = lane >> 2;
    const int ak = lane & 3;
    int buf = 0;

    for (int kt = 0; kt < KT; ++kt) {
        cp_wait<1>();          // stage kt landed
        __syncthreads();       // also: all warps done computing stage kt-1 -> safe to overwrite

        if (kt + 2 < KT) issue_stage((kt + 2) % STAGES, kt + 2);
        cp_commit();           // empty group on tail keeps wait_group accounting exact

        const float* Ab = AsBase + buf * A_STAGE;
        const float* Bb = BsBase + buf * B_STAGE;

        #pragma unroll
        for (int kk = 0; kk < 2; ++kk) {
            const int k8 = kk * 8;
            uint32_t af[WMT][4], bf[4][2];
            #pragma unroll
            for (int mt = 0; mt < WMT; ++mt) {
                const float* p = Ab + (wm * WMT * 16 + mt * 16 + ar) * AST + k8 + ak;
                af[mt][0] = f2tf_u(p[0]);
                af[mt][1] = f2tf_u(p[8 * AST]);
                af[mt][2] = f2tf_u(p[4]);
                af[mt][3] = f2tf_u(p[8 * AST + 4]);
            }
            #pragma unroll
            for (int nt = 0; nt < 4; ++nt) {
                const float* q = Bb + (k8 + ak) * BST + wn * 32 + nt * 8 + ar;
                bf[nt][0] = f2tf_u(q[0]);
                bf[nt][1] = f2tf_u(q[4 * BST]);
            }
            #pragma unroll
            for (int mt = 0; mt < WMT; ++mt)
                #pragma unroll
                for (int nt = 0; nt < 4; ++nt)
                    mma_tf32(acc[mt][nt], af[mt], bf[nt]);
        }

        buf = (buf + 1 == STAGES) ? 0 : buf + 1;
    }

    // Epilogue: bias + leaky_relu(0.01) + store
    #pragma unroll
    for (int mt = 0; mt < WMT; ++mt) {
        const int row = m0 + wm * (WMT * 16) + mt * 16 + (lane >> 2);
        #pragma unroll
        for (int nt = 0; nt < 4; ++nt) {
            const int col = wn * 32 + nt * 8 + (lane & 3) * 2;
            const float b0 = bias[col], b1 = bias[col + 1];
            float x0 = acc[mt][nt][0] + b0; x0 = x0 > 0.f ? x0 : 0.01f * x0;
            float x1 = acc[mt][nt][1] + b1; x1 = x1 > 0.f ? x1 : 0.01f * x1;
            float x2 = acc[mt][nt][2] + b0; x2 = x2 > 0.f ? x2 : 0.01f * x2;
            float x3 = acc[mt][nt][3] + b1; x3 = x3 > 0.f ? x3 : 0.01f * x3;
            *(float2*)&outp[(size_t)row * outLd + colOff + col]       = make_float2(x0, x1);
            *(float2*)&outp[(size_t)(row + 8) * outLd + colOff + col] = make_float2(x2, x3);
        }
    }
}

extern "C" void kernel_launch(void* const* d_in, const int* in_sizes, int n_in,
                              void* d_out, int out_size) {
    const float* features = (const float*)d_in[0];
    const float* W_edge   = (const float*)d_in[1];
    const float* b_edge   = (const float*)d_in[2];
    const float* W_het    = (const float*)d_in[3];
    const float* b_het    = (const float*)d_in[4];
    const int*   gid      = (const int*)d_in[5];
    float* out = (float*)d_out;

    // dynamic smem: 3*(BM*20 + 16*136) floats + BM ints
    const int smemE = (3 * (128 * 20 + 16 * 136)) * 4 + 128 * 4;   // 57344+512
    const int smemH = (3 * (64 * 20 + 16 * 136)) * 4 + 64 * 4;     // 41472+256

    cudaFuncSetAttribute(hetagg_gemm<true>,
                         cudaFuncAttributeMaxDynamicSharedMemorySize, smemE);
    cudaFuncSetAttribute(hetagg_gemm<false>,
                         cudaFuncAttributeMaxDynamicSharedMemorySize, smemH);

    dim3 g1(BATCH / 128, NUM_EDGE);
    hetagg_gemm<true><<<g1, 256, smemE>>>(features, W_edge, b_edge, gid, out);

    dim3 g2(BATCH / 64, 1);
    hetagg_gemm<false><<<g2, 256, smemH>>>(nullptr, W_het, b_het, nullptr, out);
}

// round 4
// speedup vs baseline: 2.4109x; 2.0611x over previous
#include <cuda_runtime.h>
#include <cuda_fp16.h>
#include <cstdint>

#define NUM_EDGE  14
#define NUM_NODES 10000
#define BATCH     8192
#define EDGE_IN   1536
#define HET_IN    1792
#define DOUT      128

// fp16 scratch: intermediate activations + pre-converted weights
__device__ __half g_agg[(size_t)BATCH * HET_IN];
__device__ __half g_WE [(size_t)NUM_EDGE * EDGE_IN * DOUT];
__device__ __half g_WH [(size_t)HET_IN * DOUT];

__device__ __forceinline__ uint32_t f2h2(float x, float y) {
    __half2 h = __floats2half2_rn(x, y);
    return *(uint32_t*)&h;
}

__device__ __forceinline__ void cp16(uint32_t s, const void* g) {
    asm volatile("cp.async.cg.shared.global [%0], [%1], 16;\n" :: "r"(s), "l"(g));
}
__device__ __forceinline__ void cp_commit() { asm volatile("cp.async.commit_group;\n"); }
template <int N> __device__ __forceinline__ void cp_wait() {
    asm volatile("cp.async.wait_group %0;\n" :: "n"(N));
}

__device__ __forceinline__ void ldsm_x4(uint32_t* r, uint32_t a) {
    asm volatile("ldmatrix.sync.aligned.m8n8.x4.shared.b16 {%0,%1,%2,%3}, [%4];"
        : "=r"(r[0]), "=r"(r[1]), "=r"(r[2]), "=r"(r[3]) : "r"(a));
}
__device__ __forceinline__ void ldsm_x4_t(uint32_t* r, uint32_t a) {
    asm volatile("ldmatrix.sync.aligned.m8n8.x4.trans.shared.b16 {%0,%1,%2,%3}, [%4];"
        : "=r"(r[0]), "=r"(r[1]), "=r"(r[2]), "=r"(r[3]) : "r"(a));
}
__device__ __forceinline__ void sts128(uint32_t a, uint32_t x, uint32_t y, uint32_t z, uint32_t w) {
    asm volatile("st.shared.v4.b32 [%0], {%1,%2,%3,%4};" :: "r"(a), "r"(x), "r"(y), "r"(z), "r"(w));
}

__device__ __forceinline__ void mma_f16(float* c, const uint32_t* a, const uint32_t* b) {
    asm volatile(
        "mma.sync.aligned.m16n8k16.row.col.f32.f16.f16.f32 "
        "{%0,%1,%2,%3}, {%4,%5,%6,%7}, {%8,%9}, {%0,%1,%2,%3};\n"
        : "+f"(c[0]), "+f"(c[1]), "+f"(c[2]), "+f"(c[3])
        : "r"(a[0]), "r"(a[1]), "r"(a[2]), "r"(a[3]), "r"(b[0]), "r"(b[1]));
}

// prep: fp32 -> fp16 (RN) elementwise, vectorized
__global__ void cvt_to_half(const float4* __restrict__ s, __half2* __restrict__ d, int n4) {
    int i = blockIdx.x * blockDim.x + threadIdx.x;
    if (i < n4) {
        float4 v = s[i];
        d[2 * i]     = __floats2half2_rn(v.x, v.y);
        d[2 * i + 1] = __floats2half2_rn(v.z, v.w);
    }
}

// EDGE=true : A = features[e] gathered by gid (fp32->fp16 at STS), B = g_WE[e],
//             out -> g_agg (fp16) cols e*128. BM=128, warp 64x32.
// EDGE=false: A = g_agg (fp16, cp.async), B = g_WH, out -> final fp32. BM=64, warp 32x32.
template <bool EDGE>
__global__ void __launch_bounds__(256, 2) hetagg_f16(
    const float* __restrict__ Afeat,
    const int*   __restrict__ gid,
    const float* __restrict__ ball,
    float*       __restrict__ outFinal)
{
    constexpr int BM   = EDGE ? 128 : 64;
    constexpr int WMT  = EDGE ? 4 : 2;          // m16 tiles per warp
    constexpr int K    = EDGE ? EDGE_IN : HET_IN;
    constexpr int KT   = K / 32;
    constexpr int A_ST = BM * 80;               // 80B rows: pad -> conflict-free ldmatrix
    constexpr int B_ST = 32 * 256;
    constexpr int OFF_B = 3 * A_ST;

    extern __shared__ char smem[];
    const uint32_t sb = (uint32_t)__cvta_generic_to_shared(smem);

    const int e    = EDGE ? blockIdx.y : 0;
    const int tid  = threadIdx.x;
    const int l    = tid & 31;
    const int warp = tid >> 5;
    const int wm   = warp >> 2, wn = warp & 3;
    const int m0   = blockIdx.x * BM;

    // ---- B loader (cp.async, fp16 weights): thread -> k-row tid>>3, two 16B n-chunks
    const __half* Bh = EDGE ? (g_WE + (size_t)e * EDGE_IN * DOUT) : g_WH;
    const int bk = tid >> 3;
    const int bc = (tid & 7) * 2;
    const __half* bsrc = Bh + (size_t)bk * DOUT + bc * 8;
    uint32_t bdst0, bdst1;
    {
        int c0 = bc, c1 = bc + 1;
        bdst0 = sb + OFF_B + bk * 256 + ((c0 >> 3) * 128) + (((c0 & 7) ^ (bk & 7)) * 16);
        bdst1 = sb + OFF_B + bk * 256 + ((c1 >> 3) * 128) + (((c1 & 7) ^ (bk & 7)) * 16);
    }

    // ---- A loader
    const float* ag = nullptr;      // EDGE: fp32 gather source (16 floats/thread/tile)
    const __half* agH = nullptr;    // HET: fp16 source
    uint32_t aSt = 0, adst = 0;
    if (EDGE) {
        const int arow = tid >> 1, ah = tid & 1;
        ag  = Afeat + (size_t)e * NUM_NODES * EDGE_IN
                    + (size_t)gid[m0 + arow] * EDGE_IN + ah * 16;
        aSt = sb + arow * 80 + ah * 32;
    } else {
        const int arow = tid >> 2, ac = tid & 3;
        agH  = g_agg + (size_t)(m0 + arow) * HET_IN + ac * 8;
        adst = sb + arow * 80 + ac * 16;
    }

    float4 av0, av1, av2, av3;   // A register prefetch (EDGE)
    auto ldA = [&](int kt) {
        const float4* p = (const float4*)(ag + kt * 32);
        av0 = p[0]; av1 = p[1]; av2 = p[2]; av3 = p[3];
    };
    auto stsA = [&](int s) {
        sts128(aSt + s * A_ST,
               f2h2(av0.x, av0.y), f2h2(av0.z, av0.w),
               f2h2(av1.x, av1.y), f2h2(av1.z, av1.w));
        sts128(aSt + s * A_ST + 16,
               f2h2(av2.x, av2.y), f2h2(av2.z, av2.w),
               f2h2(av3.x, av3.y), f2h2(av3.z, av3.w));
    };
    auto cpB = [&](int s, int kt) {
        const __half* src = bsrc + (size_t)kt * 32 * DOUT;
        cp16(bdst0 + s * B_ST, src);
        cp16(bdst1 + s * B_ST, src + 8);
    };
    auto cpA = [&](int s, int kt) { cp16(adst + s * A_ST, agH + kt * 32); };

    float acc[WMT][4][4];
    #pragma unroll
    for (int i = 0; i < WMT; ++i)
        #pragma unroll
        for (int j = 0; j < 4; ++j)
            #pragma unroll
            for (int q = 0; q < 4; ++q) acc[i][j][q] = 0.f;

    // Prologue: stages 0,1
    if (EDGE) {
        ldA(0); stsA(0); cpB(0, 0); cp_commit();
        ldA(1);          cpB(1, 1); cp_commit();
    } else {
        cpA(0, 0); cpB(0, 0); cp_commit();
        cpA(1, 1); cpB(1, 1); cp_commit();
    }

    int slot = 0, slotP = 1, slotF = 2;   // current, +1, +2 ring slots
    for (int kt = 0; kt < KT; ++kt) {
        cp_wait<1>();
        __syncthreads();

        if (EDGE) {
            if (kt + 1 < KT) stsA(slotP);
            if (kt + 2 < KT) { cpB(slotF, kt + 2); ldA(kt + 2); }
        } else {
            if (kt + 2 < KT) { cpA(slotF, kt + 2); cpB(slotF, kt + 2); }
        }
        cp_commit();

        // ---- compute K-tile from 'slot'
        const uint32_t Ab = sb + slot * A_ST;
        const uint32_t Bb = sb + OFF_B + slot * B_ST;
        #pragma unroll
        for (int kk = 0; kk < 2; ++kk) {
            uint32_t af[WMT][4];
            #pragma unroll
            for (int mt = 0; mt < WMT; ++mt)
                ldsm_x4(af[mt], Ab + (wm * (WMT * 16) + mt * 16 + (l & 15)) * 80
                                   + kk * 32 + (l >> 4) * 16);
            uint32_t bf[4][2];
            #pragma unroll
            for (int ntp = 0; ntp < 2; ++ntp) {
                const int krow = kk * 16 + ((l >> 3) & 1) * 8 + (l & 7);
                const int c    = wn * 4 + ntp * 2 + (l >> 4);
                uint32_t r[4];
                ldsm_x4_t(r, Bb + krow * 256 + ((c >> 3) * 128)
                             + (((c & 7) ^ (krow & 7)) << 4));
                bf[2 * ntp][0] = r[0]; bf[2 * ntp][1] = r[1];
                bf[2 * ntp + 1][0] = r[2]; bf[2 * ntp + 1][1] = r[3];
            }
            #pragma unroll
            for (int mt = 0; mt < WMT; ++mt)
                #pragma unroll
                for (int nt = 0; nt < 4; ++nt)
                    mma_f16(acc[mt][nt], af[mt], bf[nt]);
        }

        const int t = slot; slot = slotP; slotP = slotF; slotF = t;
    }

    // ---- epilogue: bias + leaky_relu(0.01)
    const float* bias = EDGE ? (ball + e * DOUT) : ball;
    #pragma unroll
    for (int mt = 0; mt < WMT; ++mt) {
        const int row = m0 + wm * (WMT * 16) + mt * 16 + (l >> 2);
        #pragma unroll
        for (int nt = 0; nt < 4; ++nt) {
            const int col = wn * 32 + nt * 8 + (l & 3) * 2;
            const float2 bv = *(const float2*)&bias[col];
            float x0 = acc[mt][nt][0] + bv.x; x0 = x0 > 0.f ? x0 : 0.01f * x0;
            float x1 = acc[mt][nt][1] + bv.y; x1 = x1 > 0.f ? x1 : 0.01f * x1;
            float x2 = acc[mt][nt][2] + bv.x; x2 = x2 > 0.f ? x2 : 0.01f * x2;
            float x3 = acc[mt][nt][3] + bv.y; x3 = x3 > 0.f ? x3 : 0.01f * x3;
            if (EDGE) {
                __half2* p0 = (__half2*)&g_agg[(size_t)row * HET_IN + e * DOUT + col];
                __half2* p1 = (__half2*)&g_agg[(size_t)(row + 8) * HET_IN + e * DOUT + col];
                *p0 = __floats2half2_rn(x0, x1);
                *p1 = __floats2half2_rn(x2, x3);
            } else {
                *(float2*)&outFinal[(size_t)row * DOUT + col]       = make_float2(x0, x1);
                *(float2*)&outFinal[(size_t)(row + 8) * DOUT + col] = make_float2(x2, x3);
            }
        }
    }
}

extern "C" void kernel_launch(void* const* d_in, const int* in_sizes, int n_in,
                              void* d_out, int out_size) {
    const float* features = (const float*)d_in[0];
    const float* W_edge   = (const float*)d_in[1];
    const float* b_edge   = (const float*)d_in[2];
    const float* W_het    = (const float*)d_in[3];
    const float* b_het    = (const float*)d_in[4];
    const int*   gid      = (const int*)d_in[5];
    float* out = (float*)d_out;

    __half* we; cudaGetSymbolAddress((void**)&we, g_WE);
    __half* wh; cudaGetSymbolAddress((void**)&wh, g_WH);

    // prep: weights fp32 -> fp16 (RN)
    const int n4e = NUM_EDGE * EDGE_IN * DOUT / 4;
    const int n4h = HET_IN * DOUT / 4;
    cvt_to_half<<<(n4e + 255) / 256, 256>>>((const float4*)W_edge, (__half2*)we, n4e);
    cvt_to_half<<<(n4h + 255) / 256, 256>>>((const float4*)W_het, (__half2*)wh, n4h);

    const int smem1 = 3 * (128 * 80) + 3 * (32 * 256);  // 55296
    const int smem2 = 3 * (64 * 80) + 3 * (32 * 256);   // 39936

    cudaFuncSetAttribute(hetagg_f16<true>,
                         cudaFuncAttributeMaxDynamicSharedMemorySize, smem1);
    cudaFuncSetAttribute(hetagg_f16<false>,
                         cudaFuncAttributeMaxDynamicSharedMemorySize, smem2);

    dim3 g1(BATCH / 128, NUM_EDGE);
    hetagg_f16<true><<<g1, 256, smem1>>>(features, gid, b_edge, nullptr);

    dim3 g2(BATCH / 64, 1);
    hetagg_f16<false><<<g2, 256, smem2>>>(nullptr, nullptr, b_het, out);
}